// round 8
// baseline (speedup 1.0000x reference)
#include <cuda_runtime.h>
#include <cuda_bf16.h>
#include <math.h>

#define E_NUM 100000
#define NN 5000

// ---------------- device scratch ----------------
__device__ __align__(16) float g_An[NN * 256];
__device__ __align__(16) float g_Bn[NN * 256];
__device__ __align__(16) float g_cut[E_NUM];
__device__ __align__(16) float g_h0[E_NUM * 256];
__device__ __align__(16) float g_h1[E_NUM * 256];
__device__ __align__(16) float g_lat[E_NUM * 256];
__device__ __align__(16) float g_wall[E_NUM * 320];
__device__ __align__(16) float g_fs1[E_NUM * 64];
__device__ __align__(16) float g_fv1[3 * E_NUM * 64];
__device__ __align__(16) float g_ns[NN * 64];
__device__ __align__(16) float g_nv[3 * NN * 64];
__device__ __align__(16) float g_ns2[NN * 64];
__device__ __align__(16) float g_nv2[3 * NN * 64];
__device__ __align__(16) float g_ts[E_NUM * 128];
__device__ __align__(16) float g_tv[3 * E_NUM * 128];
__device__ __align__(16) float g_fs3[E_NUM * 128];
__device__ __align__(16) float g_sw1[128 * 128];
__device__ __align__(16) float g_vw1[128 * 128];

__device__ __forceinline__ float siluf(float x) { return x / (1.0f + expf(-x)); }

// bf16 split: x = hi + lo
__device__ __forceinline__ void bsplit(float x, unsigned short& hb, unsigned short& lb)
{
    __nv_bfloat16 h = __float2bfloat16(x);
    hb = __bfloat16_as_ushort(h);
    float hf = __uint_as_float((unsigned)hb << 16);
    lb = __bfloat16_as_ushort(__float2bfloat16(x - hf));
}
__device__ __forceinline__ unsigned pack16(unsigned short lo, unsigned short hi)
{
    return (unsigned)lo | ((unsigned)hi << 16);
}

#define MMA_BF16(ACC, A0, A1, A2, A3, B0, B1)                                     \
    asm volatile(                                                                 \
        "mma.sync.aligned.m16n8k16.row.col.f32.bf16.bf16.f32 "                    \
        "{%0,%1,%2,%3},{%4,%5,%6,%7},{%8,%9},{%0,%1,%2,%3};"                      \
        : "+f"((ACC)[0]), "+f"((ACC)[1]), "+f"((ACC)[2]), "+f"((ACC)[3])          \
        : "r"(A0), "r"(A1), "r"(A2), "r"(A3), "r"(B0), "r"(B1))

#define LDSM4(R, ADDR)                                                            \
    asm volatile("ldmatrix.sync.aligned.m8n8.x4.shared.b16 {%0,%1,%2,%3},[%4];"   \
                 : "=r"((R)[0]), "=r"((R)[1]), "=r"((R)[2]), "=r"((R)[3])         \
                 : "r"(ADDR))

#define LDSM4T(R0, R1, R2, R3, ADDR)                                              \
    asm volatile("ldmatrix.sync.aligned.m8n8.x4.trans.shared.b16 "                \
                 "{%0,%1,%2,%3},[%4];"                                            \
                 : "=r"(R0), "=r"(R1), "=r"(R2), "=r"(R3)                         \
                 : "r"(ADDR))

// ============ 3xBF16 GEMM, 128x64 tile, ldmatrix fragments, 3 CTA/SM ============
// A smem: [2][128 rows][20 words], word w = bf16 k-pair {2w, 2w+1}
// B smem: [2][32 k-rows][36 words], word = bf16 n-pair {2c, 2c+1}
// EPI: 0 none, 1 silu, 2 cut[m]*acc, 3 residual, 4 out=acc*aux, 5 strided vec out
template <int EPI>
__global__ void __launch_bounds__(256, 3) gemm_tc(
    const float* __restrict__ A1, int K1,
    const float* __restrict__ A2, int K2,
    const float* __restrict__ B, float* __restrict__ C,
    int M, int N,
    const float* __restrict__ caux, const float* __restrict__ res_p, int comp)
{
    constexpr int BM = 128, BK = 32, BN = 64;
    constexpr int WM = 32, WN = 32, MT = 2, NT = 4;
    constexpr int AW = 20;                 // words per A row
    constexpr int BW = 36;                 // words per B k-row
    constexpr int ASZ = 2 * BM * AW;       // words per hi/lo
    constexpr int BSZ = 2 * BK * BW;

    extern __shared__ unsigned smu[];
    unsigned* AsH = smu;
    unsigned* AsL = smu + ASZ;
    unsigned* BsH = smu + 2 * ASZ;
    unsigned* BsL = smu + 2 * ASZ + BSZ;
    const unsigned baseAH = (unsigned)__cvta_generic_to_shared(AsH);
    const unsigned baseAL = (unsigned)__cvta_generic_to_shared(AsL);
    const unsigned baseBH = (unsigned)__cvta_generic_to_shared(BsH);
    const unsigned baseBL = (unsigned)__cvta_generic_to_shared(BsL);

    const int tid = threadIdx.x;
    const int lane = tid & 31;
    const int warp = tid >> 5;
    const int g = lane >> 2;
    const int kq = lane & 3;
    const int wm = warp & 3;
    const int wn = warp >> 2;
    const int m0 = blockIdx.x * BM;
    const int n0 = blockIdx.y * BN;
    const int K = K1 + K2;
    const int T = K / BK;

    // loader thread mapping
    const int ac = (tid & 7) * 4;   // A k-col base (floats)
    const int amb = tid >> 3;       // A row base
    const int bkr = tid >> 4;       // B k-row 0..15 (handles +16 too)
    const int bnc = (tid & 15) * 4; // B n base

    // ldmatrix lane offsets
    const int arow = (lane & 7) + ((lane >> 3) & 1) * 8;  // + k-select on bit4
    const int akoff = (lane >> 4) * 4;
    const int brow = (lane & 7) + ((lane >> 3) & 1) * 8;  // k within ks half
    const int bnoff = (lane >> 4) * 4;                    // n+8 select (words)

    float acc[MT][NT][4];
#pragma unroll
    for (int i = 0; i < MT; i++)
#pragma unroll
        for (int j = 0; j < NT; j++)
#pragma unroll
            for (int q = 0; q < 4; q++) acc[i][j][q] = 0.0f;

    float4 aS[4], bS[2];

    auto loadRegs = [&](int kt) {
        int k0 = kt * BK;
        const float* A; int lda, kl;
        if (k0 < K1) { A = A1; lda = K1; kl = k0; }
        else { A = A2; lda = K2; kl = k0 - K1; }
#pragma unroll
        for (int p = 0; p < 4; p++) {
            int gm = m0 + amb + p * 32;
            aS[p] = (gm < M) ? *reinterpret_cast<const float4*>(&A[(size_t)gm * lda + kl + ac])
                             : make_float4(0.f, 0.f, 0.f, 0.f);
        }
        bS[0] = *reinterpret_cast<const float4*>(&B[(size_t)(k0 + bkr) * N + n0 + bnc]);
        bS[1] = *reinterpret_cast<const float4*>(&B[(size_t)(k0 + bkr + 16) * N + n0 + bnc]);
    };
    auto splitStore = [&](int buf) {
#pragma unroll
        for (int p = 0; p < 4; p++) {
            int m = amb + p * 32;
            const float* v = reinterpret_cast<const float*>(&aS[p]);
            unsigned short h[4], l[4];
#pragma unroll
            for (int j = 0; j < 4; j++) bsplit(v[j], h[j], l[j]);
            int off = (buf * BM + m) * AW + (ac >> 1);
            *reinterpret_cast<uint2*>(&AsH[off]) = make_uint2(pack16(h[0], h[1]), pack16(h[2], h[3]));
            *reinterpret_cast<uint2*>(&AsL[off]) = make_uint2(pack16(l[0], l[1]), pack16(l[2], l[3]));
        }
#pragma unroll
        for (int p = 0; p < 2; p++) {
            int k = bkr + p * 16;
            const float* v = reinterpret_cast<const float*>(&bS[p]);
            unsigned short h[4], l[4];
#pragma unroll
            for (int j = 0; j < 4; j++) bsplit(v[j], h[j], l[j]);
            int off = (buf * BK + k) * BW + (bnc >> 1);
            *reinterpret_cast<uint2*>(&BsH[off]) = make_uint2(pack16(h[0], h[1]), pack16(h[2], h[3]));
            *reinterpret_cast<uint2*>(&BsL[off]) = make_uint2(pack16(l[0], l[1]), pack16(l[2], l[3]));
        }
    };
    auto compute = [&](int buf) {
#pragma unroll
        for (int ks = 0; ks < 2; ks++) {   // two K=16 steps per BK=32
            unsigned ah[MT][4], al[MT][4], bh[NT][2], bl[NT][2];
#pragma unroll
            for (int mt = 0; mt < MT; mt++) {
                unsigned offA = (unsigned)(((buf * BM + wm * WM + mt * 16 + arow) * AW
                                            + ks * 8 + akoff) * 4);
                LDSM4(ah[mt], baseAH + offA);
                LDSM4(al[mt], baseAL + offA);
            }
#pragma unroll
            for (int q = 0; q < 2; q++) {
                unsigned offB = (unsigned)(((buf * BK + ks * 16 + brow) * BW
                                            + wn * 16 + q * 8 + bnoff) * 4);
                LDSM4T(bh[2 * q][0], bh[2 * q][1], bh[2 * q + 1][0], bh[2 * q + 1][1],
                       baseBH + offB);
                LDSM4T(bl[2 * q][0], bl[2 * q][1], bl[2 * q + 1][0], bl[2 * q + 1][1],
                       baseBL + offB);
            }
#pragma unroll
            for (int mt = 0; mt < MT; mt++)
#pragma unroll
                for (int nt = 0; nt < NT; nt++) {
                    MMA_BF16(acc[mt][nt], al[mt][0], al[mt][1], al[mt][2], al[mt][3],
                             bh[nt][0], bh[nt][1]);
                    MMA_BF16(acc[mt][nt], ah[mt][0], ah[mt][1], ah[mt][2], ah[mt][3],
                             bl[nt][0], bl[nt][1]);
                    MMA_BF16(acc[mt][nt], ah[mt][0], ah[mt][1], ah[mt][2], ah[mt][3],
                             bh[nt][0], bh[nt][1]);
                }
        }
    };

    loadRegs(0);
    splitStore(0);
    __syncthreads();
    for (int t = 0; t < T; t++) {
        bool more = (t + 1 < T);
        if (more) loadRegs(t + 1);
        compute(t & 1);
        if (more) splitStore((t + 1) & 1);
        __syncthreads();
    }

    float rc1 = 0.f, rc2 = 0.f;
    if (EPI == 3) {
        float av = 1.0f / (1.0f + expf(-res_p[1]));
        rc1 = sqrtf(1.0f - av);
        rc2 = sqrtf(av);
    }
#pragma unroll
    for (int mt = 0; mt < MT; mt++) {
#pragma unroll
        for (int h = 0; h < 2; h++) {
            int row = m0 + wm * WM + mt * 16 + g + h * 8;
            if (row >= M) continue;
            float rs = (EPI == 2 || EPI == 3) ? caux[row] : 0.0f;
#pragma unroll
            for (int nt = 0; nt < NT; nt++) {
                int col = n0 + wn * WN + nt * 8 + kq * 2;
                float v0 = acc[mt][nt][2 * h];
                float v1 = acc[mt][nt][2 * h + 1];
                if (EPI == 1) { v0 = siluf(v0); v1 = siluf(v1); }
                else if (EPI == 2) { v0 *= rs; v1 *= rs; }
                else if (EPI == 3) {
                    float2 o = *reinterpret_cast<const float2*>(&C[(size_t)row * N + col]);
                    v0 = rc1 * o.x + rc2 * rs * v0;
                    v1 = rc1 * o.y + rc2 * rs * v1;
                }
                if (EPI == 4) {
                    float s0 = caux[(size_t)row * 128 + col];
                    float s1 = caux[(size_t)row * 128 + col + 1];
                    float2 w = make_float2(v0 * s0, v1 * s1);
                    *reinterpret_cast<float2*>(&C[(size_t)row * 512 + col]) = w;
                } else if (EPI == 5) {
                    size_t b = (size_t)row * 512 + 128 + (size_t)col * 3 + comp;
                    C[b] = v0;
                    C[b + 3] = v1;
                } else {
                    float2 w = make_float2(v0, v1);
                    *reinterpret_cast<float2*>(&C[(size_t)row * N + col]) = w;
                }
            }
        }
    }
}

// ---------------- first layer ----------------
__global__ void k_first(const float* __restrict__ radial, const float* __restrict__ elen,
                        const int* __restrict__ eidx, const float* __restrict__ w0r)
{
    int e = blockIdx.x;
    int t = threadIdx.x;
    __shared__ float r[8];
    if (t < 8) r[t] = radial[e * 8 + t];
    if (t == 0) {
        float x = elen[e] * 0.2f;
        float x2 = x * x;
        float x6 = x2 * x2 * x2;
        float o = 1.0f - 28.0f * x6 + 48.0f * x6 * x - 21.0f * x6 * x2;
        g_cut[e] = (x < 1.0f) ? o : 0.0f;
    }
    __syncthreads();
    int c = eidx[e];
    int n = eidx[E_NUM + e];
    float acc = g_An[c * 256 + t] + g_Bn[n * 256 + t];
#pragma unroll
    for (int j = 0; j < 8; j++) acc = fmaf(r[j], w0r[j * 256 + t], acc);
    g_h0[(size_t)e * 256 + t] = siluf(acc);
}

__global__ void k_zero()
{
    int i = blockIdx.x * 256 + threadIdx.x;
    if (i < NN * 64) {
        g_ns[i] = 0.f;
        g_nv[i] = 0.f;
        g_nv[NN * 64 + i] = 0.f;
        g_nv[2 * NN * 64 + i] = 0.f;
    }
}

__global__ void k_scatter(const float* __restrict__ ang, const int* __restrict__ center, int S)
{
    int idx = blockIdx.x * blockDim.x + threadIdx.x;
    if (idx >= E_NUM * 64) return;
    int e = idx >> 6, u = idx & 63;
    float4 sh = *reinterpret_cast<const float4*>(&ang[e * 4]);
    const float* w = &g_wall[(size_t)e * S];
    float we0 = w[2 * u], we1 = w[2 * u + 1];
    int c = center[e];
    atomicAdd(&g_ns[c * 64 + u], we0 * sh.x);
    atomicAdd(&g_nv[c * 64 + u], we1 * sh.y);
    atomicAdd(&g_nv[NN * 64 + c * 64 + u], we1 * sh.z);
    atomicAdd(&g_nv[2 * NN * 64 + c * 64 + u], we1 * sh.w);
}

__global__ void k_nodelin(const float* __restrict__ W)
{
    int nn = blockIdx.x;
    int t = threadIdx.x;
    __shared__ float sin_[256];
    int ch = t >> 6, v = t & 63;
    float val = (ch == 0) ? g_ns[nn * 64 + v] : g_nv[(ch - 1) * NN * 64 + nn * 64 + v];
    sin_[t] = val * 0.05f;
    __syncthreads();
    const float* Wm = W + (ch == 0 ? 0 : 64 * 64);
    float acc = 0.f;
#pragma unroll
    for (int u = 0; u < 64; u++) acc = fmaf(sin_[ch * 64 + u], Wm[u * 64 + v], acc);
    if (ch == 0) g_ns2[nn * 64 + v] = acc;
    else g_nv2[(ch - 1) * NN * 64 + nn * 64 + v] = acc;
}

__device__ __forceinline__ void tp_tail(int e, int u, int c,
                                        float f, float fx, float fy, float fz)
{
    float s2 = g_ns2[c * 64 + u];
    float vx = g_nv2[c * 64 + u];
    float vy = g_nv2[NN * 64 + c * 64 + u];
    float vz = g_nv2[2 * NN * 64 + c * 64 + u];
    const float IS3 = 0.57735026918962576f;
    size_t b = (size_t)e * 128 + u;
    g_ts[b] = f * s2;
    g_ts[b + 64] = (fx * vx + fy * vy + fz * vz) * IS3;
    g_tv[b] = f * vx * IS3;
    g_tv[b + 64] = fx * s2 * IS3;
    g_tv[(size_t)E_NUM * 128 + b] = f * vy * IS3;
    g_tv[(size_t)E_NUM * 128 + b + 64] = fy * s2 * IS3;
    g_tv[(size_t)2 * E_NUM * 128 + b] = f * vz * IS3;
    g_tv[(size_t)2 * E_NUM * 128 + b + 64] = fz * s2 * IS3;
}

__global__ void k_tp0(const float* __restrict__ ang, const int* __restrict__ center)
{
    int idx = blockIdx.x * blockDim.x + threadIdx.x;
    if (idx >= E_NUM * 64) return;
    int e = idx >> 6, u = idx & 63;
    float4 sh = *reinterpret_cast<const float4*>(&ang[e * 4]);
    const float* w = &g_wall[(size_t)e * 320];
    float gate = w[128 + u];
    float wf0 = w[192 + 2 * u], wf1 = w[193 + 2 * u];
    float f = wf0 * sh.x * gate;
    float fx = wf1 * sh.y * gate;
    float fy = wf1 * sh.z * gate;
    float fz = wf1 * sh.w * gate;
    tp_tail(e, u, center[e], f, fx, fy, fz);
}

__global__ void k_tp1(const float* __restrict__ ang, const int* __restrict__ center)
{
    int idx = blockIdx.x * blockDim.x + threadIdx.x;
    if (idx >= E_NUM * 64) return;
    int e = idx >> 6, u = idx & 63;
    float gate = g_wall[(size_t)e * 192 + 128 + u];
    float f = g_fs1[idx] * gate;
    float fx = g_fv1[idx] * gate;
    float fy = g_fv1[E_NUM * 64 + idx] * gate;
    float fz = g_fv1[2 * E_NUM * 64 + idx] * gate;
    tp_tail(e, u, center[e], f, fx, fy, fz);
}

__global__ void k_prep(const float* __restrict__ sw, const float* __restrict__ vw)
{
    int idx = blockIdx.x * 256 + threadIdx.x;
    if (idx >= 2 * 2 * 64 * 64) return;
    int v = idx & 63;
    int u = (idx >> 6) & 63;
    int o = (idx >> 12) & 1;
    int i = (idx >> 13) & 1;
    int dst = (i * 64 + u) * 128 + o * 64 + v;
    g_sw1[dst] = sw[idx];
    g_vw1[dst] = vw[idx];
}

// ---------------- host launch ----------------
template <typename T>
static float* symaddr(const T& sym)
{
    void* p = nullptr;
    cudaGetSymbolAddress(&p, sym);
    return (float*)p;
}

static const int SMEM = (2 * (2 * 128 * 20) + 2 * (2 * 32 * 36)) * 4;  // 59392

extern "C" void kernel_launch(void* const* d_in, const int* in_sizes, int n_in,
                              void* d_out, int out_size)
{
    const float* node_attrs = (const float*)d_in[0];
    const float* radial = (const float*)d_in[1];
    const float* ang = (const float*)d_in[2];
    const float* elen = (const float*)d_in[3];
    const int* eidx = (const int*)d_in[4];
    const float* tb_w0 = (const float*)d_in[5];
    const float* tb_w1 = (const float*)d_in[6];
    const float* tb_w2 = (const float*)d_in[7];
    const float* lat1_w0 = (const float*)d_in[8];
    const float* lat1_w1 = (const float*)d_in[9];
    const float* env0_w = (const float*)d_in[10];
    const float* env1_w = (const float*)d_in[11];
    const float* envlin0 = (const float*)d_in[12];
    const float* envlin1 = (const float*)d_in[13];
    const float* lin0_sw = (const float*)d_in[14];
    const float* lin0_vw = (const float*)d_in[15];
    const float* lin1_sw = (const float*)d_in[16];
    const float* lin1_vw = (const float*)d_in[17];
    const float* fin_w0 = (const float*)d_in[18];
    const float* fin_w1 = (const float*)d_in[19];
    const float* res_p = (const float*)d_in[20];
    float* out = (float*)d_out;

    float* An = symaddr(g_An);
    float* Bn = symaddr(g_Bn);
    float* cut = symaddr(g_cut);
    float* h0 = symaddr(g_h0);
    float* h1 = symaddr(g_h1);
    float* lat = symaddr(g_lat);
    float* wall = symaddr(g_wall);
    float* fs1 = symaddr(g_fs1);
    float* fv1 = symaddr(g_fv1);
    float* ts = symaddr(g_ts);
    float* tv = symaddr(g_tv);
    float* fs3 = symaddr(g_fs3);
    float* sw1 = symaddr(g_sw1);
    float* vw1 = symaddr(g_vw1);

    (void)in_sizes; (void)n_in; (void)out_size;

    cudaFuncSetAttribute(gemm_tc<0>, cudaFuncAttributeMaxDynamicSharedMemorySize, SMEM);
    cudaFuncSetAttribute(gemm_tc<1>, cudaFuncAttributeMaxDynamicSharedMemorySize, SMEM);
    cudaFuncSetAttribute(gemm_tc<2>, cudaFuncAttributeMaxDynamicSharedMemorySize, SMEM);
    cudaFuncSetAttribute(gemm_tc<3>, cudaFuncAttributeMaxDynamicSharedMemorySize, SMEM);
    cudaFuncSetAttribute(gemm_tc<4>, cudaFuncAttributeMaxDynamicSharedMemorySize, SMEM);
    cudaFuncSetAttribute(gemm_tc<5>, cudaFuncAttributeMaxDynamicSharedMemorySize, SMEM);

    auto g64 = [](int M, int N) { return dim3((M + 127) / 128, N / 64); };
    const int EW = (E_NUM * 64 + 255) / 256;
    const int ZB = (NN * 64 + 255) / 256;
    const int E64c = E_NUM * 64;
    const int E128c = E_NUM * 128;

    // node precompute
    gemm_tc<0><<<g64(NN, 256), 256, SMEM>>>(node_attrs, 64, nullptr, 0, tb_w0, An, NN, 256, nullptr, nullptr, 0);
    gemm_tc<0><<<g64(NN, 256), 256, SMEM>>>(node_attrs, 64, nullptr, 0, tb_w0 + 64 * 256, Bn, NN, 256, nullptr, nullptr, 0);

    // first layer + cut
    k_first<<<E_NUM, 256>>>(radial, elen, eidx, tb_w0 + 128 * 256);

    // tb MLP
    gemm_tc<1><<<g64(E_NUM, 256), 256, SMEM>>>(h0, 256, nullptr, 0, tb_w1, h1, E_NUM, 256, nullptr, nullptr, 0);
    gemm_tc<2><<<g64(E_NUM, 256), 256, SMEM>>>(h1, 256, nullptr, 0, tb_w2, lat, E_NUM, 256, cut, nullptr, 0);

    // env0
    gemm_tc<0><<<g64(E_NUM, 320), 256, SMEM>>>(lat, 256, nullptr, 0, env0_w, wall, E_NUM, 320, nullptr, nullptr, 0);
    k_zero<<<ZB, 256>>>();
    k_scatter<<<EW, 256>>>(ang, eidx, 320);
    k_nodelin<<<NN, 256>>>(envlin0);
    k_tp0<<<EW, 256>>>(ang, eidx);

    // lin0
    gemm_tc<0><<<g64(E_NUM, 64), 256, SMEM>>>(ts, 128, nullptr, 0, lin0_sw, fs1, E_NUM, 64, nullptr, nullptr, 0);
    for (int c = 0; c < 3; c++)
        gemm_tc<0><<<g64(E_NUM, 64), 256, SMEM>>>(tv + (size_t)c * E128c, 128, nullptr, 0, lin0_vw,
                                                  fv1 + (size_t)c * E64c, E_NUM, 64, nullptr, nullptr, 0);

    // lat1 MLP + residual
    gemm_tc<1><<<g64(E_NUM, 256), 256, SMEM>>>(lat, 256, ts, 128, lat1_w0, h1, E_NUM, 256, nullptr, nullptr, 0);
    gemm_tc<3><<<g64(E_NUM, 256), 256, SMEM>>>(h1, 256, nullptr, 0, lat1_w1, lat, E_NUM, 256, cut, res_p, 0);

    // env1
    gemm_tc<0><<<g64(E_NUM, 192), 256, SMEM>>>(lat, 256, nullptr, 0, env1_w, wall, E_NUM, 192, nullptr, nullptr, 0);
    k_zero<<<ZB, 256>>>();
    k_scatter<<<EW, 256>>>(ang, eidx, 192);
    k_nodelin<<<NN, 256>>>(envlin1);
    k_tp1<<<EW, 256>>>(ang, eidx);

    // lin1: sw -> fs3; vw -> out directly (vector half)
    k_prep<<<(2 * 2 * 64 * 64 + 255) / 256, 256>>>(lin1_sw, lin1_vw);
    gemm_tc<0><<<g64(E_NUM, 128), 256, SMEM>>>(ts, 128, nullptr, 0, sw1, fs3, E_NUM, 128, nullptr, nullptr, 0);
    for (int c = 0; c < 3; c++)
        gemm_tc<5><<<g64(E_NUM, 128), 256, SMEM>>>(tv + (size_t)c * E128c, 128, nullptr, 0, vw1,
                                                   out, E_NUM, 128, nullptr, nullptr, c);

    // fin MLP
    gemm_tc<1><<<g64(E_NUM, 256), 256, SMEM>>>(lat, 256, ts, 128, fin_w0, h1, E_NUM, 256, nullptr, nullptr, 0);
    gemm_tc<4><<<g64(E_NUM, 128), 256, SMEM>>>(h1, 256, nullptr, 0, fin_w1, out, E_NUM, 128, fs3, nullptr, 0);
}

// round 9
// speedup vs baseline: 1.0453x; 1.0453x over previous
#include <cuda_runtime.h>
#include <cuda_bf16.h>
#include <math.h>

#define E_NUM 100000
#define NN 5000

// ---------------- device scratch ----------------
__device__ __align__(16) float g_An[NN * 256];
__device__ __align__(16) float g_Bn[NN * 256];
__device__ __align__(16) float g_cut[E_NUM];
__device__ __align__(16) float g_h0[E_NUM * 256];
__device__ __align__(16) float g_h1[E_NUM * 256];
__device__ __align__(16) float g_lat[E_NUM * 256];
__device__ __align__(16) float g_wall[E_NUM * 320];
__device__ __align__(16) float g_fs1[E_NUM * 64];
__device__ __align__(16) float g_fv1[3 * E_NUM * 64];
__device__ __align__(16) float g_ns[NN * 64];
__device__ __align__(16) float g_nv[3 * NN * 64];
__device__ __align__(16) float g_ns2[NN * 64];
__device__ __align__(16) float g_nv2[3 * NN * 64];
__device__ __align__(16) float g_ts[E_NUM * 128];
__device__ __align__(16) float g_tv[3 * E_NUM * 128];
__device__ __align__(16) float g_fs3[E_NUM * 128];
__device__ __align__(16) float g_sw1[128 * 128];
__device__ __align__(16) float g_vw1[128 * 128];

__device__ __forceinline__ float siluf(float x) { return x / (1.0f + expf(-x)); }

// bf16 split: x = hi + lo
__device__ __forceinline__ void bsplit(float x, unsigned short& hb, unsigned short& lb)
{
    __nv_bfloat16 h = __float2bfloat16(x);
    hb = __bfloat16_as_ushort(h);
    float hf = __uint_as_float((unsigned)hb << 16);
    lb = __bfloat16_as_ushort(__float2bfloat16(x - hf));
}
__device__ __forceinline__ unsigned pack16(unsigned short lo, unsigned short hi)
{
    return (unsigned)lo | ((unsigned)hi << 16);
}

#define MMA_BF16(ACC, A0, A1, A2, A3, B0, B1)                                     \
    asm volatile(                                                                 \
        "mma.sync.aligned.m16n8k16.row.col.f32.bf16.bf16.f32 "                    \
        "{%0,%1,%2,%3},{%4,%5,%6,%7},{%8,%9},{%0,%1,%2,%3};"                      \
        : "+f"((ACC)[0]), "+f"((ACC)[1]), "+f"((ACC)[2]), "+f"((ACC)[3])          \
        : "r"(A0), "r"(A1), "r"(A2), "r"(A3), "r"(B0), "r"(B1))

#define LDSM4(R, ADDR)                                                            \
    asm volatile("ldmatrix.sync.aligned.m8n8.x4.shared.b16 {%0,%1,%2,%3},[%4];"   \
                 : "=r"((R)[0]), "=r"((R)[1]), "=r"((R)[2]), "=r"((R)[3])         \
                 : "r"(ADDR))

#define LDSM4T(R0, R1, R2, R3, ADDR)                                              \
    asm volatile("ldmatrix.sync.aligned.m8n8.x4.trans.shared.b16 "                \
                 "{%0,%1,%2,%3},[%4];"                                            \
                 : "=r"(R0), "=r"(R1), "=r"(R2), "=r"(R3)                         \
                 : "r"(ADDR))

// ============ 3xBF16 GEMM, 128x64 tile, ldmatrix fragments, 3 CTA/SM ============
// Grid: x = N-tile (fastest -> consecutive CTAs share the A m-tile in L2),
//       y = M-tile, z = component (A/C offset by strideA/strideC).
// EPI: 0 none, 1 silu, 2 cut[m]*acc, 3 residual, 4 out=acc*aux, 5 strided vec out
template <int EPI>
__global__ void __launch_bounds__(256, 3) gemm_tc(
    const float* __restrict__ A1, int K1,
    const float* __restrict__ A2, int K2,
    const float* __restrict__ B, float* __restrict__ C,
    int M, int N,
    const float* __restrict__ caux, const float* __restrict__ res_p,
    long strideA, long strideC)
{
    constexpr int BM = 128, BK = 32, BN = 64;
    constexpr int WM = 32, WN = 32, MT = 2, NT = 4;
    constexpr int AW = 20;
    constexpr int BW = 36;
    constexpr int ASZ = 2 * BM * AW;
    constexpr int BSZ = 2 * BK * BW;

    extern __shared__ unsigned smu[];
    unsigned* AsH = smu;
    unsigned* AsL = smu + ASZ;
    unsigned* BsH = smu + 2 * ASZ;
    unsigned* BsL = smu + 2 * ASZ + BSZ;
    const unsigned baseAH = (unsigned)__cvta_generic_to_shared(AsH);
    const unsigned baseAL = (unsigned)__cvta_generic_to_shared(AsL);
    const unsigned baseBH = (unsigned)__cvta_generic_to_shared(BsH);
    const unsigned baseBL = (unsigned)__cvta_generic_to_shared(BsL);

    const int comp = blockIdx.z;
    A1 += (size_t)comp * strideA;
    C += (size_t)comp * ((EPI == 5) ? 1 : strideC);

    const int tid = threadIdx.x;
    const int lane = tid & 31;
    const int warp = tid >> 5;
    const int g = lane >> 2;
    const int kq = lane & 3;
    const int wm = warp & 3;
    const int wn = warp >> 2;
    const int m0 = blockIdx.y * BM;
    const int n0 = blockIdx.x * BN;
    const int K = K1 + K2;
    const int T = K / BK;

    const int ac = (tid & 7) * 4;
    const int amb = tid >> 3;
    const int bkr = tid >> 4;
    const int bnc = (tid & 15) * 4;

    const int arow = (lane & 7) + ((lane >> 3) & 1) * 8;
    const int akoff = (lane >> 4) * 4;
    const int brow = (lane & 7) + ((lane >> 3) & 1) * 8;
    const int bnoff = (lane >> 4) * 4;

    float acc[MT][NT][4];
#pragma unroll
    for (int i = 0; i < MT; i++)
#pragma unroll
        for (int j = 0; j < NT; j++)
#pragma unroll
            for (int q = 0; q < 4; q++) acc[i][j][q] = 0.0f;

    float4 aS[4], bS[2];

    auto loadRegs = [&](int kt) {
        int k0 = kt * BK;
        const float* A; int lda, kl;
        if (k0 < K1) { A = A1; lda = K1; kl = k0; }
        else { A = A2; lda = K2; kl = k0 - K1; }
#pragma unroll
        for (int p = 0; p < 4; p++) {
            int gm = m0 + amb + p * 32;
            aS[p] = (gm < M) ? *reinterpret_cast<const float4*>(&A[(size_t)gm * lda + kl + ac])
                             : make_float4(0.f, 0.f, 0.f, 0.f);
        }
        bS[0] = *reinterpret_cast<const float4*>(&B[(size_t)(k0 + bkr) * N + n0 + bnc]);
        bS[1] = *reinterpret_cast<const float4*>(&B[(size_t)(k0 + bkr + 16) * N + n0 + bnc]);
    };
    auto splitStore = [&](int buf) {
#pragma unroll
        for (int p = 0; p < 4; p++) {
            int m = amb + p * 32;
            const float* v = reinterpret_cast<const float*>(&aS[p]);
            unsigned short h[4], l[4];
#pragma unroll
            for (int j = 0; j < 4; j++) bsplit(v[j], h[j], l[j]);
            int off = (buf * BM + m) * AW + (ac >> 1);
            *reinterpret_cast<uint2*>(&AsH[off]) = make_uint2(pack16(h[0], h[1]), pack16(h[2], h[3]));
            *reinterpret_cast<uint2*>(&AsL[off]) = make_uint2(pack16(l[0], l[1]), pack16(l[2], l[3]));
        }
#pragma unroll
        for (int p = 0; p < 2; p++) {
            int k = bkr + p * 16;
            const float* v = reinterpret_cast<const float*>(&bS[p]);
            unsigned short h[4], l[4];
#pragma unroll
            for (int j = 0; j < 4; j++) bsplit(v[j], h[j], l[j]);
            int off = (buf * BK + k) * BW + (bnc >> 1);
            *reinterpret_cast<uint2*>(&BsH[off]) = make_uint2(pack16(h[0], h[1]), pack16(h[2], h[3]));
            *reinterpret_cast<uint2*>(&BsL[off]) = make_uint2(pack16(l[0], l[1]), pack16(l[2], l[3]));
        }
    };
    auto compute = [&](int buf) {
#pragma unroll
        for (int ks = 0; ks < 2; ks++) {
            unsigned ah[MT][4], al[MT][4], bh[NT][2], bl[NT][2];
#pragma unroll
            for (int mt = 0; mt < MT; mt++) {
                unsigned offA = (unsigned)(((buf * BM + wm * WM + mt * 16 + arow) * AW
                                            + ks * 8 + akoff) * 4);
                LDSM4(ah[mt], baseAH + offA);
                LDSM4(al[mt], baseAL + offA);
            }
#pragma unroll
            for (int q = 0; q < 2; q++) {
                unsigned offB = (unsigned)(((buf * BK + ks * 16 + brow) * BW
                                            + wn * 16 + q * 8 + bnoff) * 4);
                LDSM4T(bh[2 * q][0], bh[2 * q][1], bh[2 * q + 1][0], bh[2 * q + 1][1],
                       baseBH + offB);
                LDSM4T(bl[2 * q][0], bl[2 * q][1], bl[2 * q + 1][0], bl[2 * q + 1][1],
                       baseBL + offB);
            }
#pragma unroll
            for (int mt = 0; mt < MT; mt++)
#pragma unroll
                for (int nt = 0; nt < NT; nt++) {
                    MMA_BF16(acc[mt][nt], al[mt][0], al[mt][1], al[mt][2], al[mt][3],
                             bh[nt][0], bh[nt][1]);
                    MMA_BF16(acc[mt][nt], ah[mt][0], ah[mt][1], ah[mt][2], ah[mt][3],
                             bl[nt][0], bl[nt][1]);
                    MMA_BF16(acc[mt][nt], ah[mt][0], ah[mt][1], ah[mt][2], ah[mt][3],
                             bh[nt][0], bh[nt][1]);
                }
        }
    };

    loadRegs(0);
    splitStore(0);
    __syncthreads();
    for (int t = 0; t < T; t++) {
        bool more = (t + 1 < T);
        if (more) loadRegs(t + 1);
        compute(t & 1);
        if (more) splitStore((t + 1) & 1);
        __syncthreads();
    }

    float rc1 = 0.f, rc2 = 0.f;
    if (EPI == 3) {
        float av = 1.0f / (1.0f + expf(-res_p[1]));
        rc1 = sqrtf(1.0f - av);
        rc2 = sqrtf(av);
    }
#pragma unroll
    for (int mt = 0; mt < MT; mt++) {
#pragma unroll
        for (int h = 0; h < 2; h++) {
            int row = m0 + wm * WM + mt * 16 + g + h * 8;
            if (row >= M) continue;
            float rs = (EPI == 2 || EPI == 3) ? caux[row] : 0.0f;
#pragma unroll
            for (int nt = 0; nt < NT; nt++) {
                int col = n0 + wn * WN + nt * 8 + kq * 2;
                float v0 = acc[mt][nt][2 * h];
                float v1 = acc[mt][nt][2 * h + 1];
                if (EPI == 1) { v0 = siluf(v0); v1 = siluf(v1); }
                else if (EPI == 2) { v0 *= rs; v1 *= rs; }
                else if (EPI == 3) {
                    float2 o = *reinterpret_cast<const float2*>(&C[(size_t)row * N + col]);
                    v0 = rc1 * o.x + rc2 * rs * v0;
                    v1 = rc1 * o.y + rc2 * rs * v1;
                }
                if (EPI == 4) {
                    float s0 = caux[(size_t)row * 128 + col];
                    float s1 = caux[(size_t)row * 128 + col + 1];
                    float2 w = make_float2(v0 * s0, v1 * s1);
                    *reinterpret_cast<float2*>(&C[(size_t)row * 512 + col]) = w;
                } else if (EPI == 5) {
                    size_t b = (size_t)row * 512 + 128 + (size_t)col * 3;
                    C[b] = v0;
                    C[b + 3] = v1;
                } else {
                    float2 w = make_float2(v0, v1);
                    *reinterpret_cast<float2*>(&C[(size_t)row * N + col]) = w;
                }
            }
        }
    }
}

// ---------------- first layer ----------------
__global__ void k_first(const float* __restrict__ radial, const float* __restrict__ elen,
                        const int* __restrict__ eidx, const float* __restrict__ w0r)
{
    int e = blockIdx.x;
    int t = threadIdx.x;
    __shared__ float r[8];
    if (t < 8) r[t] = radial[e * 8 + t];
    if (t == 0) {
        float x = elen[e] * 0.2f;
        float x2 = x * x;
        float x6 = x2 * x2 * x2;
        float o = 1.0f - 28.0f * x6 + 48.0f * x6 * x - 21.0f * x6 * x2;
        g_cut[e] = (x < 1.0f) ? o : 0.0f;
    }
    __syncthreads();
    int c = eidx[e];
    int n = eidx[E_NUM + e];
    float acc = g_An[c * 256 + t] + g_Bn[n * 256 + t];
#pragma unroll
    for (int j = 0; j < 8; j++) acc = fmaf(r[j], w0r[j * 256 + t], acc);
    g_h0[(size_t)e * 256 + t] = siluf(acc);
}

__global__ void k_zero()
{
    int i = blockIdx.x * 256 + threadIdx.x;
    if (i < NN * 64) {
        g_ns[i] = 0.f;
        g_nv[i] = 0.f;
        g_nv[NN * 64 + i] = 0.f;
        g_nv[2 * NN * 64 + i] = 0.f;
    }
}

__global__ void k_scatter(const float* __restrict__ ang, const int* __restrict__ center, int S)
{
    int idx = blockIdx.x * blockDim.x + threadIdx.x;
    if (idx >= E_NUM * 64) return;
    int e = idx >> 6, u = idx & 63;
    float4 sh = *reinterpret_cast<const float4*>(&ang[e * 4]);
    const float* w = &g_wall[(size_t)e * S];
    float we0 = w[2 * u], we1 = w[2 * u + 1];
    int c = center[e];
    atomicAdd(&g_ns[c * 64 + u], we0 * sh.x);
    atomicAdd(&g_nv[c * 64 + u], we1 * sh.y);
    atomicAdd(&g_nv[NN * 64 + c * 64 + u], we1 * sh.z);
    atomicAdd(&g_nv[2 * NN * 64 + c * 64 + u], we1 * sh.w);
}

__global__ void k_nodelin(const float* __restrict__ W)
{
    int nn = blockIdx.x;
    int t = threadIdx.x;
    __shared__ float sin_[256];
    int ch = t >> 6, v = t & 63;
    float val = (ch == 0) ? g_ns[nn * 64 + v] : g_nv[(ch - 1) * NN * 64 + nn * 64 + v];
    sin_[t] = val * 0.05f;
    __syncthreads();
    const float* Wm = W + (ch == 0 ? 0 : 64 * 64);
    float acc = 0.f;
#pragma unroll
    for (int u = 0; u < 64; u++) acc = fmaf(sin_[ch * 64 + u], Wm[u * 64 + v], acc);
    if (ch == 0) g_ns2[nn * 64 + v] = acc;
    else g_nv2[(ch - 1) * NN * 64 + nn * 64 + v] = acc;
}

__device__ __forceinline__ void tp_tail(int e, int u, int c,
                                        float f, float fx, float fy, float fz)
{
    float s2 = g_ns2[c * 64 + u];
    float vx = g_nv2[c * 64 + u];
    float vy = g_nv2[NN * 64 + c * 64 + u];
    float vz = g_nv2[2 * NN * 64 + c * 64 + u];
    const float IS3 = 0.57735026918962576f;
    size_t b = (size_t)e * 128 + u;
    g_ts[b] = f * s2;
    g_ts[b + 64] = (fx * vx + fy * vy + fz * vz) * IS3;
    g_tv[b] = f * vx * IS3;
    g_tv[b + 64] = fx * s2 * IS3;
    g_tv[(size_t)E_NUM * 128 + b] = f * vy * IS3;
    g_tv[(size_t)E_NUM * 128 + b + 64] = fy * s2 * IS3;
    g_tv[(size_t)2 * E_NUM * 128 + b] = f * vz * IS3;
    g_tv[(size_t)2 * E_NUM * 128 + b + 64] = fz * s2 * IS3;
}

__global__ void k_tp0(const float* __restrict__ ang, const int* __restrict__ center)
{
    int idx = blockIdx.x * blockDim.x + threadIdx.x;
    if (idx >= E_NUM * 64) return;
    int e = idx >> 6, u = idx & 63;
    float4 sh = *reinterpret_cast<const float4*>(&ang[e * 4]);
    const float* w = &g_wall[(size_t)e * 320];
    float gate = w[128 + u];
    float wf0 = w[192 + 2 * u], wf1 = w[193 + 2 * u];
    float f = wf0 * sh.x * gate;
    float fx = wf1 * sh.y * gate;
    float fy = wf1 * sh.z * gate;
    float fz = wf1 * sh.w * gate;
    tp_tail(e, u, center[e], f, fx, fy, fz);
}

__global__ void k_tp1(const float* __restrict__ ang, const int* __restrict__ center)
{
    int idx = blockIdx.x * blockDim.x + threadIdx.x;
    if (idx >= E_NUM * 64) return;
    int e = idx >> 6, u = idx & 63;
    float gate = g_wall[(size_t)e * 192 + 128 + u];
    float f = g_fs1[idx] * gate;
    float fx = g_fv1[idx] * gate;
    float fy = g_fv1[E_NUM * 64 + idx] * gate;
    float fz = g_fv1[2 * E_NUM * 64 + idx] * gate;
    tp_tail(e, u, center[e], f, fx, fy, fz);
}

__global__ void k_prep(const float* __restrict__ sw, const float* __restrict__ vw)
{
    int idx = blockIdx.x * 256 + threadIdx.x;
    if (idx >= 2 * 2 * 64 * 64) return;
    int v = idx & 63;
    int u = (idx >> 6) & 63;
    int o = (idx >> 12) & 1;
    int i = (idx >> 13) & 1;
    int dst = (i * 64 + u) * 128 + o * 64 + v;
    g_sw1[dst] = sw[idx];
    g_vw1[dst] = vw[idx];
}

// ---------------- host launch ----------------
template <typename T>
static float* symaddr(const T& sym)
{
    void* p = nullptr;
    cudaGetSymbolAddress(&p, sym);
    return (float*)p;
}

static const int SMEM = (2 * (2 * 128 * 20) + 2 * (2 * 32 * 36)) * 4;  // 59392

extern "C" void kernel_launch(void* const* d_in, const int* in_sizes, int n_in,
                              void* d_out, int out_size)
{
    const float* node_attrs = (const float*)d_in[0];
    const float* radial = (const float*)d_in[1];
    const float* ang = (const float*)d_in[2];
    const float* elen = (const float*)d_in[3];
    const int* eidx = (const int*)d_in[4];
    const float* tb_w0 = (const float*)d_in[5];
    const float* tb_w1 = (const float*)d_in[6];
    const float* tb_w2 = (const float*)d_in[7];
    const float* lat1_w0 = (const float*)d_in[8];
    const float* lat1_w1 = (const float*)d_in[9];
    const float* env0_w = (const float*)d_in[10];
    const float* env1_w = (const float*)d_in[11];
    const float* envlin0 = (const float*)d_in[12];
    const float* envlin1 = (const float*)d_in[13];
    const float* lin0_sw = (const float*)d_in[14];
    const float* lin0_vw = (const float*)d_in[15];
    const float* lin1_sw = (const float*)d_in[16];
    const float* lin1_vw = (const float*)d_in[17];
    const float* fin_w0 = (const float*)d_in[18];
    const float* fin_w1 = (const float*)d_in[19];
    const float* res_p = (const float*)d_in[20];
    float* out = (float*)d_out;

    float* An = symaddr(g_An);
    float* Bn = symaddr(g_Bn);
    float* cut = symaddr(g_cut);
    float* h0 = symaddr(g_h0);
    float* h1 = symaddr(g_h1);
    float* lat = symaddr(g_lat);
    float* wall = symaddr(g_wall);
    float* fs1 = symaddr(g_fs1);
    float* fv1 = symaddr(g_fv1);
    float* ts = symaddr(g_ts);
    float* tv = symaddr(g_tv);
    float* fs3 = symaddr(g_fs3);
    float* sw1 = symaddr(g_sw1);
    float* vw1 = symaddr(g_vw1);

    (void)in_sizes; (void)n_in; (void)out_size;

    cudaFuncSetAttribute(gemm_tc<0>, cudaFuncAttributeMaxDynamicSharedMemorySize, SMEM);
    cudaFuncSetAttribute(gemm_tc<1>, cudaFuncAttributeMaxDynamicSharedMemorySize, SMEM);
    cudaFuncSetAttribute(gemm_tc<2>, cudaFuncAttributeMaxDynamicSharedMemorySize, SMEM);
    cudaFuncSetAttribute(gemm_tc<3>, cudaFuncAttributeMaxDynamicSharedMemorySize, SMEM);
    cudaFuncSetAttribute(gemm_tc<4>, cudaFuncAttributeMaxDynamicSharedMemorySize, SMEM);
    cudaFuncSetAttribute(gemm_tc<5>, cudaFuncAttributeMaxDynamicSharedMemorySize, SMEM);

    // grid: x = N tiles (fastest -> A-tile L2 sharing), y = M tiles, z = components
    auto g64 = [](int M, int N, int Z) { return dim3(N / 64, (M + 127) / 128, Z); };
    const int EW = (E_NUM * 64 + 255) / 256;
    const int ZB = (NN * 64 + 255) / 256;
    const long E64c = E_NUM * 64;
    const long E128c = (long)E_NUM * 128;

    // node precompute
    gemm_tc<0><<<g64(NN, 256, 1), 256, SMEM>>>(node_attrs, 64, nullptr, 0, tb_w0, An, NN, 256, nullptr, nullptr, 0, 0);
    gemm_tc<0><<<g64(NN, 256, 1), 256, SMEM>>>(node_attrs, 64, nullptr, 0, tb_w0 + 64 * 256, Bn, NN, 256, nullptr, nullptr, 0, 0);

    // first layer + cut
    k_first<<<E_NUM, 256>>>(radial, elen, eidx, tb_w0 + 128 * 256);

    // tb MLP
    gemm_tc<1><<<g64(E_NUM, 256, 1), 256, SMEM>>>(h0, 256, nullptr, 0, tb_w1, h1, E_NUM, 256, nullptr, nullptr, 0, 0);
    gemm_tc<2><<<g64(E_NUM, 256, 1), 256, SMEM>>>(h1, 256, nullptr, 0, tb_w2, lat, E_NUM, 256, cut, nullptr, 0, 0);

    // env0
    gemm_tc<0><<<g64(E_NUM, 320, 1), 256, SMEM>>>(lat, 256, nullptr, 0, env0_w, wall, E_NUM, 320, nullptr, nullptr, 0, 0);
    k_zero<<<ZB, 256>>>();
    k_scatter<<<EW, 256>>>(ang, eidx, 320);
    k_nodelin<<<NN, 256>>>(envlin0);
    k_tp0<<<EW, 256>>>(ang, eidx);

    // lin0: z=0 -> ts@sw -> fs1; z=1..3 -> tv[c]@vw -> fv1[c]
    gemm_tc<0><<<g64(E_NUM, 64, 1), 256, SMEM>>>(ts, 128, nullptr, 0, lin0_sw, fs1, E_NUM, 64, nullptr, nullptr, 0, 0);
    gemm_tc<0><<<g64(E_NUM, 64, 3), 256, SMEM>>>(tv, 128, nullptr, 0, lin0_vw, fv1, E_NUM, 64, nullptr, nullptr, E128c, E64c);

    // lat1 MLP + residual
    gemm_tc<1><<<g64(E_NUM, 256, 1), 256, SMEM>>>(lat, 256, ts, 128, lat1_w0, h1, E_NUM, 256, nullptr, nullptr, 0, 0);
    gemm_tc<3><<<g64(E_NUM, 256, 1), 256, SMEM>>>(h1, 256, nullptr, 0, lat1_w1, lat, E_NUM, 256, cut, res_p, 0, 0);

    // env1
    gemm_tc<0><<<g64(E_NUM, 192, 1), 256, SMEM>>>(lat, 256, nullptr, 0, env1_w, wall, E_NUM, 192, nullptr, nullptr, 0, 0);
    k_zero<<<ZB, 256>>>();
    k_scatter<<<EW, 256>>>(ang, eidx, 192);
    k_nodelin<<<NN, 256>>>(envlin1);
    k_tp1<<<EW, 256>>>(ang, eidx);

    // lin1: sw -> fs3; vw -> out vector half (EPI5, z-component offset +1 float each)
    k_prep<<<(2 * 2 * 64 * 64 + 255) / 256, 256>>>(lin1_sw, lin1_vw);
    gemm_tc<0><<<g64(E_NUM, 128, 1), 256, SMEM>>>(ts, 128, nullptr, 0, sw1, fs3, E_NUM, 128, nullptr, nullptr, 0, 0);
    gemm_tc<5><<<g64(E_NUM, 128, 3), 256, SMEM>>>(tv, 128, nullptr, 0, vw1, out, E_NUM, 128, nullptr, nullptr, E128c, 0);

    // fin MLP
    gemm_tc<1><<<g64(E_NUM, 256, 1), 256, SMEM>>>(lat, 256, ts, 128, fin_w0, h1, E_NUM, 256, nullptr, nullptr, 0, 0);
    gemm_tc<4><<<g64(E_NUM, 128, 1), 256, SMEM>>>(h1, 256, nullptr, 0, fin_w1, out, E_NUM, 128, fs3, nullptr, 0, 0);
}

// round 10
// speedup vs baseline: 1.1473x; 1.0976x over previous
#include <cuda_runtime.h>
#include <cuda_bf16.h>
#include <math.h>

#define E_NUM 100000
#define NN 5000

// ---------------- device scratch ----------------
__device__ __align__(16) float g_An[NN * 256];
__device__ __align__(16) float g_Bn[NN * 256];
__device__ __align__(16) float g_cut[E_NUM];
__device__ __align__(16) float g_h0[E_NUM * 256];
__device__ __align__(16) float g_h1[E_NUM * 256];
__device__ __align__(16) float g_lat[E_NUM * 256];
__device__ __align__(16) float g_wall[E_NUM * 320];
__device__ __align__(16) float g_fs1[E_NUM * 64];
__device__ __align__(16) float g_fv1[3 * E_NUM * 64];
__device__ __align__(16) float g_ns[NN * 64];
__device__ __align__(16) float g_nv[3 * NN * 64];
__device__ __align__(16) float g_ns2[NN * 64];
__device__ __align__(16) float g_nv2[3 * NN * 64];
__device__ __align__(16) float g_ts[E_NUM * 128];
__device__ __align__(16) float g_tv[3 * E_NUM * 128];
__device__ __align__(16) float g_fs3[E_NUM * 128];
__device__ __align__(16) float g_sw1[128 * 128];
__device__ __align__(16) float g_vw1[128 * 128];

__device__ __forceinline__ float siluf(float x) { return x / (1.0f + expf(-x)); }

__device__ __forceinline__ void bsplit(float x, unsigned short& hb, unsigned short& lb)
{
    __nv_bfloat16 h = __float2bfloat16(x);
    hb = __bfloat16_as_ushort(h);
    float hf = __uint_as_float((unsigned)hb << 16);
    lb = __bfloat16_as_ushort(__float2bfloat16(x - hf));
}
__device__ __forceinline__ unsigned pack16(unsigned short lo, unsigned short hi)
{
    return (unsigned)lo | ((unsigned)hi << 16);
}

#define MMA_BF16(ACC, A0, A1, A2, A3, B0, B1)                                     \
    asm volatile(                                                                 \
        "mma.sync.aligned.m16n8k16.row.col.f32.bf16.bf16.f32 "                    \
        "{%0,%1,%2,%3},{%4,%5,%6,%7},{%8,%9},{%0,%1,%2,%3};"                      \
        : "+f"((ACC)[0]), "+f"((ACC)[1]), "+f"((ACC)[2]), "+f"((ACC)[3])          \
        : "r"(A0), "r"(A1), "r"(A2), "r"(A3), "r"(B0), "r"(B1))

#define LDSM4(R, ADDR)                                                            \
    asm volatile("ldmatrix.sync.aligned.m8n8.x4.shared.b16 {%0,%1,%2,%3},[%4];"   \
                 : "=r"((R)[0]), "=r"((R)[1]), "=r"((R)[2]), "=r"((R)[3])         \
                 : "r"(ADDR))

#define LDSM4T(R0, R1, R2, R3, ADDR)                                              \
    asm volatile("ldmatrix.sync.aligned.m8n8.x4.trans.shared.b16 "                \
                 "{%0,%1,%2,%3},[%4];"                                            \
                 : "=r"(R0), "=r"(R1), "=r"(R2), "=r"(R3)                         \
                 : "r"(ADDR))

// ============ 3xBF16 GEMM, BM=128 x BN tile, ldmatrix fragments ============
// BN=64: 4x2 warps (WM=32), 3 CTA/SM. BN=128: 2x4 warps (WM=64), 2 CTA/SM.
// Grid: x = N-tile (fastest -> A-tile L2 sharing), y = M-tile, z = component.
// EPI: 0 none, 1 silu, 2 cut[m]*acc, 3 residual, 4 out=acc*aux, 5 strided vec out
template <int BN, int EPI>
__global__ void __launch_bounds__(256, (BN == 64) ? 3 : 2) gemm_tc(
    const float* __restrict__ A1, int K1,
    const float* __restrict__ A2, int K2,
    const float* __restrict__ B, float* __restrict__ C,
    int M, int N,
    const float* __restrict__ caux, const float* __restrict__ res_p,
    long strideA, long strideC)
{
    constexpr int BM = 128, BK = 32;
    constexpr int WM = (BN == 64) ? 32 : 64;
    constexpr int WN = 32;
    constexpr int MT = WM / 16;
    constexpr int NT = 4;
    constexpr int NWM = BM / WM;               // warps in m: 4 or 2
    constexpr int AW = 20;
    constexpr int BW = BN / 2 + 4;             // 36 or 68
    constexpr int ASZ = 2 * BM * AW;
    constexpr int BSZ = 2 * BK * BW;
    constexpr int F4 = BN / 4;                 // float4 per B row: 16 or 32
    constexpr int RPP = 256 / F4;              // B rows per pass: 16 or 8
    constexpr int NP = BK / RPP;               // passes: 2 or 4

    extern __shared__ unsigned smu[];
    unsigned* AsH = smu;
    unsigned* AsL = smu + ASZ;
    unsigned* BsH = smu + 2 * ASZ;
    unsigned* BsL = smu + 2 * ASZ + BSZ;
    const unsigned baseAH = (unsigned)__cvta_generic_to_shared(AsH);
    const unsigned baseAL = (unsigned)__cvta_generic_to_shared(AsL);
    const unsigned baseBH = (unsigned)__cvta_generic_to_shared(BsH);
    const unsigned baseBL = (unsigned)__cvta_generic_to_shared(BsL);

    const int comp = blockIdx.z;
    A1 += (size_t)comp * strideA;
    C += (size_t)comp * ((EPI == 5) ? 1 : strideC);

    const int tid = threadIdx.x;
    const int lane = tid & 31;
    const int warp = tid >> 5;
    const int g = lane >> 2;
    const int kq = lane & 3;
    const int wm = warp & (NWM - 1);
    const int wn = warp / NWM;
    const int m0 = blockIdx.y * BM;
    const int n0 = blockIdx.x * BN;
    const int K = K1 + K2;
    const int T = K / BK;

    const int ac = (tid & 7) * 4;
    const int amb = tid >> 3;
    const int brb = tid / F4;                  // B k-row base
    const int bnc = (tid & (F4 - 1)) * 4;      // B n base (floats)

    const int arow = (lane & 7) + ((lane >> 3) & 1) * 8;
    const int akoff = (lane >> 4) * 4;
    const int brow = (lane & 7) + ((lane >> 3) & 1) * 8;
    const int bnoff = (lane >> 4) * 4;

    float acc[MT][NT][4];
#pragma unroll
    for (int i = 0; i < MT; i++)
#pragma unroll
        for (int j = 0; j < NT; j++)
#pragma unroll
            for (int q = 0; q < 4; q++) acc[i][j][q] = 0.0f;

    float4 aS[4], bS[NP];

    auto loadRegs = [&](int kt) {
        int k0 = kt * BK;
        const float* A; int lda, kl;
        if (k0 < K1) { A = A1; lda = K1; kl = k0; }
        else { A = A2; lda = K2; kl = k0 - K1; }
#pragma unroll
        for (int p = 0; p < 4; p++) {
            int gm = m0 + amb + p * 32;
            aS[p] = (gm < M) ? *reinterpret_cast<const float4*>(&A[(size_t)gm * lda + kl + ac])
                             : make_float4(0.f, 0.f, 0.f, 0.f);
        }
#pragma unroll
        for (int p = 0; p < NP; p++)
            bS[p] = *reinterpret_cast<const float4*>(&B[(size_t)(k0 + brb + p * RPP) * N + n0 + bnc]);
    };
    auto splitStore = [&](int buf) {
#pragma unroll
        for (int p = 0; p < 4; p++) {
            int m = amb + p * 32;
            const float* v = reinterpret_cast<const float*>(&aS[p]);
            unsigned short h[4], l[4];
#pragma unroll
            for (int j = 0; j < 4; j++) bsplit(v[j], h[j], l[j]);
            int off = (buf * BM + m) * AW + (ac >> 1);
            *reinterpret_cast<uint2*>(&AsH[off]) = make_uint2(pack16(h[0], h[1]), pack16(h[2], h[3]));
            *reinterpret_cast<uint2*>(&AsL[off]) = make_uint2(pack16(l[0], l[1]), pack16(l[2], l[3]));
        }
#pragma unroll
        for (int p = 0; p < NP; p++) {
            int k = brb + p * RPP;
            const float* v = reinterpret_cast<const float*>(&bS[p]);
            unsigned short h[4], l[4];
#pragma unroll
            for (int j = 0; j < 4; j++) bsplit(v[j], h[j], l[j]);
            int off = (buf * BK + k) * BW + (bnc >> 1);
            *reinterpret_cast<uint2*>(&BsH[off]) = make_uint2(pack16(h[0], h[1]), pack16(h[2], h[3]));
            *reinterpret_cast<uint2*>(&BsL[off]) = make_uint2(pack16(l[0], l[1]), pack16(l[2], l[3]));
        }
    };
    auto compute = [&](int buf) {
#pragma unroll
        for (int ks = 0; ks < 2; ks++) {
            unsigned ah[MT][4], al[MT][4], bh[NT][2], bl[NT][2];
#pragma unroll
            for (int mt = 0; mt < MT; mt++) {
                unsigned offA = (unsigned)(((buf * BM + wm * WM + mt * 16 + arow) * AW
                                            + ks * 8 + akoff) * 4);
                LDSM4(ah[mt], baseAH + offA);
                LDSM4(al[mt], baseAL + offA);
            }
#pragma unroll
            for (int q = 0; q < 2; q++) {
                unsigned offB = (unsigned)(((buf * BK + ks * 16 + brow) * BW
                                            + wn * 16 + q * 8 + bnoff) * 4);
                LDSM4T(bh[2 * q][0], bh[2 * q][1], bh[2 * q + 1][0], bh[2 * q + 1][1],
                       baseBH + offB);
                LDSM4T(bl[2 * q][0], bl[2 * q][1], bl[2 * q + 1][0], bl[2 * q + 1][1],
                       baseBL + offB);
            }
#pragma unroll
            for (int mt = 0; mt < MT; mt++)
#pragma unroll
                for (int nt = 0; nt < NT; nt++) {
                    MMA_BF16(acc[mt][nt], al[mt][0], al[mt][1], al[mt][2], al[mt][3],
                             bh[nt][0], bh[nt][1]);
                    MMA_BF16(acc[mt][nt], ah[mt][0], ah[mt][1], ah[mt][2], ah[mt][3],
                             bl[nt][0], bl[nt][1]);
                    MMA_BF16(acc[mt][nt], ah[mt][0], ah[mt][1], ah[mt][2], ah[mt][3],
                             bh[nt][0], bh[nt][1]);
                }
        }
    };

    loadRegs(0);
    splitStore(0);
    __syncthreads();
    for (int t = 0; t < T; t++) {
        bool more = (t + 1 < T);
        if (more) loadRegs(t + 1);
        compute(t & 1);
        if (more) splitStore((t + 1) & 1);
        __syncthreads();
    }

    float rc1 = 0.f, rc2 = 0.f;
    if (EPI == 3) {
        float av = 1.0f / (1.0f + expf(-res_p[1]));
        rc1 = sqrtf(1.0f - av);
        rc2 = sqrtf(av);
    }
#pragma unroll
    for (int mt = 0; mt < MT; mt++) {
#pragma unroll
        for (int h = 0; h < 2; h++) {
            int row = m0 + wm * WM + mt * 16 + g + h * 8;
            if (row >= M) continue;
            float rs = (EPI == 2 || EPI == 3) ? caux[row] : 0.0f;
#pragma unroll
            for (int nt = 0; nt < NT; nt++) {
                int col = n0 + wn * WN + nt * 8 + kq * 2;
                float v0 = acc[mt][nt][2 * h];
                float v1 = acc[mt][nt][2 * h + 1];
                if (EPI == 1) { v0 = siluf(v0); v1 = siluf(v1); }
                else if (EPI == 2) { v0 *= rs; v1 *= rs; }
                else if (EPI == 3) {
                    float2 o = *reinterpret_cast<const float2*>(&C[(size_t)row * N + col]);
                    v0 = rc1 * o.x + rc2 * rs * v0;
                    v1 = rc1 * o.y + rc2 * rs * v1;
                }
                if (EPI == 4) {
                    float s0 = caux[(size_t)row * 128 + col];
                    float s1 = caux[(size_t)row * 128 + col + 1];
                    float2 w = make_float2(v0 * s0, v1 * s1);
                    *reinterpret_cast<float2*>(&C[(size_t)row * 512 + col]) = w;
                } else if (EPI == 5) {
                    size_t b = (size_t)row * 512 + 128 + (size_t)col * 3;
                    C[b] = v0;
                    C[b + 3] = v1;
                } else {
                    float2 w = make_float2(v0, v1);
                    *reinterpret_cast<float2*>(&C[(size_t)row * N + col]) = w;
                }
            }
        }
    }
}

// ---------------- first layer ----------------
__global__ void k_first(const float* __restrict__ radial, const float* __restrict__ elen,
                        const int* __restrict__ eidx, const float* __restrict__ w0r)
{
    int e = blockIdx.x;
    int t = threadIdx.x;
    __shared__ float r[8];
    if (t < 8) r[t] = radial[e * 8 + t];
    if (t == 0) {
        float x = elen[e] * 0.2f;
        float x2 = x * x;
        float x6 = x2 * x2 * x2;
        float o = 1.0f - 28.0f * x6 + 48.0f * x6 * x - 21.0f * x6 * x2;
        g_cut[e] = (x < 1.0f) ? o : 0.0f;
    }
    __syncthreads();
    int c = eidx[e];
    int n = eidx[E_NUM + e];
    float acc = g_An[c * 256 + t] + g_Bn[n * 256 + t];
#pragma unroll
    for (int j = 0; j < 8; j++) acc = fmaf(r[j], w0r[j * 256 + t], acc);
    g_h0[(size_t)e * 256 + t] = siluf(acc);
}

__global__ void k_zero()
{
    int i = blockIdx.x * 256 + threadIdx.x;
    if (i < NN * 64) {
        g_ns[i] = 0.f;
        g_nv[i] = 0.f;
        g_nv[NN * 64 + i] = 0.f;
        g_nv[2 * NN * 64 + i] = 0.f;
    }
}

__global__ void k_scatter(const float* __restrict__ ang, const int* __restrict__ center, int S)
{
    int idx = blockIdx.x * blockDim.x + threadIdx.x;
    if (idx >= E_NUM * 64) return;
    int e = idx >> 6, u = idx & 63;
    float4 sh = *reinterpret_cast<const float4*>(&ang[e * 4]);
    const float* w = &g_wall[(size_t)e * S];
    float we0 = w[2 * u], we1 = w[2 * u + 1];
    int c = center[e];
    atomicAdd(&g_ns[c * 64 + u], we0 * sh.x);
    atomicAdd(&g_nv[c * 64 + u], we1 * sh.y);
    atomicAdd(&g_nv[NN * 64 + c * 64 + u], we1 * sh.z);
    atomicAdd(&g_nv[2 * NN * 64 + c * 64 + u], we1 * sh.w);
}

__global__ void k_nodelin(const float* __restrict__ W)
{
    int nn = blockIdx.x;
    int t = threadIdx.x;
    __shared__ float sin_[256];
    int ch = t >> 6, v = t & 63;
    float val = (ch == 0) ? g_ns[nn * 64 + v] : g_nv[(ch - 1) * NN * 64 + nn * 64 + v];
    sin_[t] = val * 0.05f;
    __syncthreads();
    const float* Wm = W + (ch == 0 ? 0 : 64 * 64);
    float acc = 0.f;
#pragma unroll
    for (int u = 0; u < 64; u++) acc = fmaf(sin_[ch * 64 + u], Wm[u * 64 + v], acc);
    if (ch == 0) g_ns2[nn * 64 + v] = acc;
    else g_nv2[(ch - 1) * NN * 64 + nn * 64 + v] = acc;
}

__device__ __forceinline__ void tp_tail(int e, int u, int c,
                                        float f, float fx, float fy, float fz)
{
    float s2 = g_ns2[c * 64 + u];
    float vx = g_nv2[c * 64 + u];
    float vy = g_nv2[NN * 64 + c * 64 + u];
    float vz = g_nv2[2 * NN * 64 + c * 64 + u];
    const float IS3 = 0.57735026918962576f;
    size_t b = (size_t)e * 128 + u;
    g_ts[b] = f * s2;
    g_ts[b + 64] = (fx * vx + fy * vy + fz * vz) * IS3;
    g_tv[b] = f * vx * IS3;
    g_tv[b + 64] = fx * s2 * IS3;
    g_tv[(size_t)E_NUM * 128 + b] = f * vy * IS3;
    g_tv[(size_t)E_NUM * 128 + b + 64] = fy * s2 * IS3;
    g_tv[(size_t)2 * E_NUM * 128 + b] = f * vz * IS3;
    g_tv[(size_t)2 * E_NUM * 128 + b + 64] = fz * s2 * IS3;
}

__global__ void k_tp0(const float* __restrict__ ang, const int* __restrict__ center)
{
    int idx = blockIdx.x * blockDim.x + threadIdx.x;
    if (idx >= E_NUM * 64) return;
    int e = idx >> 6, u = idx & 63;
    float4 sh = *reinterpret_cast<const float4*>(&ang[e * 4]);
    const float* w = &g_wall[(size_t)e * 320];
    float gate = w[128 + u];
    float wf0 = w[192 + 2 * u], wf1 = w[193 + 2 * u];
    float f = wf0 * sh.x * gate;
    float fx = wf1 * sh.y * gate;
    float fy = wf1 * sh.z * gate;
    float fz = wf1 * sh.w * gate;
    tp_tail(e, u, center[e], f, fx, fy, fz);
}

__global__ void k_tp1(const float* __restrict__ ang, const int* __restrict__ center)
{
    int idx = blockIdx.x * blockDim.x + threadIdx.x;
    if (idx >= E_NUM * 64) return;
    int e = idx >> 6, u = idx & 63;
    float gate = g_wall[(size_t)e * 192 + 128 + u];
    float f = g_fs1[idx] * gate;
    float fx = g_fv1[idx] * gate;
    float fy = g_fv1[E_NUM * 64 + idx] * gate;
    float fz = g_fv1[2 * E_NUM * 64 + idx] * gate;
    tp_tail(e, u, center[e], f, fx, fy, fz);
}

__global__ void k_prep(const float* __restrict__ sw, const float* __restrict__ vw)
{
    int idx = blockIdx.x * 256 + threadIdx.x;
    if (idx >= 2 * 2 * 64 * 64) return;
    int v = idx & 63;
    int u = (idx >> 6) & 63;
    int o = (idx >> 12) & 1;
    int i = (idx >> 13) & 1;
    int dst = (i * 64 + u) * 128 + o * 64 + v;
    g_sw1[dst] = sw[idx];
    g_vw1[dst] = vw[idx];
}

// ---------------- host launch ----------------
template <typename T>
static float* symaddr(const T& sym)
{
    void* p = nullptr;
    cudaGetSymbolAddress(&p, sym);
    return (float*)p;
}

static const int SMEM64 = (2 * (2 * 128 * 20) + 2 * (2 * 32 * 36)) * 4;   // 59392
static const int SMEM128 = (2 * (2 * 128 * 20) + 2 * (2 * 32 * 68)) * 4;  // 75776

extern "C" void kernel_launch(void* const* d_in, const int* in_sizes, int n_in,
                              void* d_out, int out_size)
{
    const float* node_attrs = (const float*)d_in[0];
    const float* radial = (const float*)d_in[1];
    const float* ang = (const float*)d_in[2];
    const float* elen = (const float*)d_in[3];
    const int* eidx = (const int*)d_in[4];
    const float* tb_w0 = (const float*)d_in[5];
    const float* tb_w1 = (const float*)d_in[6];
    const float* tb_w2 = (const float*)d_in[7];
    const float* lat1_w0 = (const float*)d_in[8];
    const float* lat1_w1 = (const float*)d_in[9];
    const float* env0_w = (const float*)d_in[10];
    const float* env1_w = (const float*)d_in[11];
    const float* envlin0 = (const float*)d_in[12];
    const float* envlin1 = (const float*)d_in[13];
    const float* lin0_sw = (const float*)d_in[14];
    const float* lin0_vw = (const float*)d_in[15];
    const float* lin1_sw = (const float*)d_in[16];
    const float* lin1_vw = (const float*)d_in[17];
    const float* fin_w0 = (const float*)d_in[18];
    const float* fin_w1 = (const float*)d_in[19];
    const float* res_p = (const float*)d_in[20];
    float* out = (float*)d_out;

    float* An = symaddr(g_An);
    float* Bn = symaddr(g_Bn);
    float* cut = symaddr(g_cut);
    float* h0 = symaddr(g_h0);
    float* h1 = symaddr(g_h1);
    float* lat = symaddr(g_lat);
    float* wall = symaddr(g_wall);
    float* fs1 = symaddr(g_fs1);
    float* fv1 = symaddr(g_fv1);
    float* ts = symaddr(g_ts);
    float* tv = symaddr(g_tv);
    float* fs3 = symaddr(g_fs3);
    float* sw1 = symaddr(g_sw1);
    float* vw1 = symaddr(g_vw1);

    (void)in_sizes; (void)n_in; (void)out_size;

    cudaFuncSetAttribute(gemm_tc<64, 0>, cudaFuncAttributeMaxDynamicSharedMemorySize, SMEM64);
    cudaFuncSetAttribute(gemm_tc<128, 0>, cudaFuncAttributeMaxDynamicSharedMemorySize, SMEM128);
    cudaFuncSetAttribute(gemm_tc<128, 1>, cudaFuncAttributeMaxDynamicSharedMemorySize, SMEM128);
    cudaFuncSetAttribute(gemm_tc<128, 2>, cudaFuncAttributeMaxDynamicSharedMemorySize, SMEM128);
    cudaFuncSetAttribute(gemm_tc<128, 3>, cudaFuncAttributeMaxDynamicSharedMemorySize, SMEM128);
    cudaFuncSetAttribute(gemm_tc<128, 4>, cudaFuncAttributeMaxDynamicSharedMemorySize, SMEM128);
    cudaFuncSetAttribute(gemm_tc<128, 5>, cudaFuncAttributeMaxDynamicSharedMemorySize, SMEM128);

    // grid: x = N tiles (fastest -> A-tile L2 sharing), y = M tiles, z = components
    auto gN = [](int M, int N, int Z, int BN) { return dim3(N / BN, (M + 127) / 128, Z); };
    const int EW = (E_NUM * 64 + 255) / 256;
    const int ZB = (NN * 64 + 255) / 256;
    const long E64c = E_NUM * 64;
    const long E128c = (long)E_NUM * 128;

    // node precompute
    gemm_tc<128, 0><<<gN(NN, 256, 1, 128), 256, SMEM128>>>(node_attrs, 64, nullptr, 0, tb_w0, An, NN, 256, nullptr, nullptr, 0, 0);
    gemm_tc<128, 0><<<gN(NN, 256, 1, 128), 256, SMEM128>>>(node_attrs, 64, nullptr, 0, tb_w0 + 64 * 256, Bn, NN, 256, nullptr, nullptr, 0, 0);

    // first layer + cut
    k_first<<<E_NUM, 256>>>(radial, elen, eidx, tb_w0 + 128 * 256);

    // tb MLP
    gemm_tc<128, 1><<<gN(E_NUM, 256, 1, 128), 256, SMEM128>>>(h0, 256, nullptr, 0, tb_w1, h1, E_NUM, 256, nullptr, nullptr, 0, 0);
    gemm_tc<128, 2><<<gN(E_NUM, 256, 1, 128), 256, SMEM128>>>(h1, 256, nullptr, 0, tb_w2, lat, E_NUM, 256, cut, nullptr, 0, 0);

    // env0 (N=320 -> BN=64 path)
    gemm_tc<64, 0><<<gN(E_NUM, 320, 1, 64), 256, SMEM64>>>(lat, 256, nullptr, 0, env0_w, wall, E_NUM, 320, nullptr, nullptr, 0, 0);
    k_zero<<<ZB, 256>>>();
    k_scatter<<<EW, 256>>>(ang, eidx, 320);
    k_nodelin<<<NN, 256>>>(envlin0);
    k_tp0<<<EW, 256>>>(ang, eidx);

    // lin0 (N=64)
    gemm_tc<64, 0><<<gN(E_NUM, 64, 1, 64), 256, SMEM64>>>(ts, 128, nullptr, 0, lin0_sw, fs1, E_NUM, 64, nullptr, nullptr, 0, 0);
    gemm_tc<64, 0><<<gN(E_NUM, 64, 3, 64), 256, SMEM64>>>(tv, 128, nullptr, 0, lin0_vw, fv1, E_NUM, 64, nullptr, nullptr, E128c, E64c);

    // lat1 MLP + residual
    gemm_tc<128, 1><<<gN(E_NUM, 256, 1, 128), 256, SMEM128>>>(lat, 256, ts, 128, lat1_w0, h1, E_NUM, 256, nullptr, nullptr, 0, 0);
    gemm_tc<128, 3><<<gN(E_NUM, 256, 1, 128), 256, SMEM128>>>(h1, 256, nullptr, 0, lat1_w1, lat, E_NUM, 256, cut, res_p, 0, 0);

    // env1 (N=192 -> BN=64 path)
    gemm_tc<64, 0><<<gN(E_NUM, 192, 1, 64), 256, SMEM64>>>(lat, 256, nullptr, 0, env1_w, wall, E_NUM, 192, nullptr, nullptr, 0, 0);
    k_zero<<<ZB, 256>>>();
    k_scatter<<<EW, 256>>>(ang, eidx, 192);
    k_nodelin<<<NN, 256>>>(envlin1);
    k_tp1<<<EW, 256>>>(ang, eidx);

    // lin1: sw -> fs3; vw -> out vector half
    k_prep<<<(2 * 2 * 64 * 64 + 255) / 256, 256>>>(lin1_sw, lin1_vw);
    gemm_tc<128, 0><<<gN(E_NUM, 128, 1, 128), 256, SMEM128>>>(ts, 128, nullptr, 0, sw1, fs3, E_NUM, 128, nullptr, nullptr, 0, 0);
    gemm_tc<128, 5><<<gN(E_NUM, 128, 3, 128), 256, SMEM128>>>(tv, 128, nullptr, 0, vw1, out, E_NUM, 128, nullptr, nullptr, E128c, 0);

    // fin MLP
    gemm_tc<128, 1><<<gN(E_NUM, 256, 1, 128), 256, SMEM128>>>(lat, 256, ts, 128, fin_w0, h1, E_NUM, 256, nullptr, nullptr, 0, 0);
    gemm_tc<128, 4><<<gN(E_NUM, 128, 1, 128), 256, SMEM128>>>(h1, 256, nullptr, 0, fin_w1, out, E_NUM, 128, fs3, nullptr, 0, 0);
}